// round 13
// baseline (speedup 1.0000x reference)
#include <cuda_runtime.h>
#include <cuda_fp16.h>
#include <cuda_bf16.h>
#include <cstdint>
#include <cstddef>

// ---------------------------------------------------------------------------
// out[8192,4096] = x[8192,4096] @ W_eff[4096,4096]^T + bias
//   W_eff = scale*qweight + lora_A @ lora_B   (LoRA folded into the weight)
// Base-ISA path (harness compiles compute_103, no 'a' features):
//   cp.async + ldmatrix + mma.sync.m16n8k16 f16->f32.
// R11 == R8 (never benched due to infra failure): loads issued before
// compute each stage, double-buffered ldmatrix fragments across k16 steps,
// fused prep kernel (cvt + weff overlap).
// ---------------------------------------------------------------------------
#define M_TOTAL 8192
#define K_TOTAL 4096
#define N_TOTAL 4096
#define LRANK   16

#define BLOCK_M 128
#define BLOCK_N 128
#define BLOCK_K 64                       // halves per stage
#define NSTAGES (K_TOTAL / BLOCK_K)      // 64
#define DEPTH   3

#define A_BYTES (BLOCK_M * BLOCK_K * 2)  // 16384
#define B_BYTES (BLOCK_N * BLOCK_K * 2)  // 16384
#define STAGE_BYTES (A_BYTES + B_BYTES)  // 32768
#define SMEM_DYN (DEPTH * STAGE_BYTES + 1024)   // 99328

// 4 warps = 2 (M) x 2 (N); warp tile 64 x 64 (4 m16 x 8 n8 mma tiles).

// Fused prep grid split
#define CVT_BLOCKS  16384                // (M*K/8)/256
#define WEFF_BX     (K_TOTAL / 256)      // 16
#define WEFF_BY     (N_TOTAL / 32)       // 128
#define WEFF_BLOCKS (WEFF_BX * WEFF_BY)  // 2048

// ---------------------------------------------------------------------------
// Scratch (static device globals: allocation-free rule)
// ---------------------------------------------------------------------------
__device__ __align__(1024) __half g_xh[(size_t)M_TOTAL * K_TOTAL];    // 64 MB
__device__ __align__(1024) __half g_weff[(size_t)N_TOTAL * K_TOTAL];  // 32 MB

// ---------------------------------------------------------------------------
// Helpers
// ---------------------------------------------------------------------------
__device__ __forceinline__ uint32_t smem_to_u32(const void* p) {
    uint32_t a;
    asm("{ .reg .u64 t; cvta.to.shared.u64 t, %1; cvt.u32.u64 %0, t; }"
        : "=r"(a) : "l"(p));
    return a;
}

__device__ __forceinline__ void cp16(uint32_t dst, const void* src) {
    asm volatile("cp.async.cg.shared.global [%0], [%1], 16;"
                 :: "r"(dst), "l"(src) : "memory");
}

// SW128 swizzle for 128-byte rows: XOR bits[6:4] with bits[9:7]
__device__ __forceinline__ uint32_t swz(uint32_t byte) {
    return byte ^ ((byte >> 3) & 0x70);
}

__device__ __forceinline__ uint32_t tile_addr(uint32_t base, int row, int kcol) {
    return base + swz((uint32_t)(row * 128 + kcol * 2));
}

__device__ __forceinline__ void ldsm_x4(uint32_t* r, uint32_t addr) {
    asm volatile("ldmatrix.sync.aligned.m8n8.x4.shared.b16 {%0,%1,%2,%3}, [%4];"
                 : "=r"(r[0]), "=r"(r[1]), "=r"(r[2]), "=r"(r[3]) : "r"(addr));
}

__device__ __forceinline__ void mma16816(float* c, const uint32_t* a,
                                         const uint32_t* b) {
    asm volatile(
        "mma.sync.aligned.m16n8k16.row.col.f32.f16.f16.f32 "
        "{%0,%1,%2,%3}, {%4,%5,%6,%7}, {%8,%9}, {%0,%1,%2,%3};"
        : "+f"(c[0]), "+f"(c[1]), "+f"(c[2]), "+f"(c[3])
        : "r"(a[0]), "r"(a[1]), "r"(a[2]), "r"(a[3]), "r"(b[0]), "r"(b[1]));
}

// ---------------------------------------------------------------------------
// Fused prep: blocks [0, CVT_BLOCKS) convert x fp32->fp16;
//             blocks [CVT_BLOCKS, +WEFF_BLOCKS) build W_eff.
// Independent outputs -> the DRAM-bound cvt and load-bound weff overlap.
// ---------------------------------------------------------------------------
__global__ void __launch_bounds__(256) prep_kernel(
        const float4* __restrict__ x,
        const int* __restrict__ q, const float* __restrict__ scale,
        const float* __restrict__ lA, const float* __restrict__ lB) {
    if (blockIdx.x < CVT_BLOCKS) {
        size_t i = (size_t)blockIdx.x * 256 + threadIdx.x;   // i < M*K/8
        float4 a = x[2 * i];
        float4 b = x[2 * i + 1];
        __half2 h0 = __floats2half2_rn(a.x, a.y);
        __half2 h1 = __floats2half2_rn(a.z, a.w);
        __half2 h2 = __floats2half2_rn(b.x, b.y);
        __half2 h3 = __floats2half2_rn(b.z, b.w);
        uint4 o;
        o.x = *reinterpret_cast<uint32_t*>(&h0);
        o.y = *reinterpret_cast<uint32_t*>(&h1);
        o.z = *reinterpret_cast<uint32_t*>(&h2);
        o.w = *reinterpret_cast<uint32_t*>(&h3);
        reinterpret_cast<uint4*>(g_xh)[i] = o;
        return;
    }
    // W_eff part
    __shared__ float bs[LRANK][33];
    const int b  = blockIdx.x - CVT_BLOCKS;
    const int k  = (b % WEFF_BX) * 256 + threadIdx.x;
    const int n0 = (b / WEFF_BX) * 32;
    for (int idx = threadIdx.x; idx < LRANK * 32; idx += 256) {
        int r = idx >> 5, j = idx & 31;
        bs[r][j] = lB[r * N_TOTAL + n0 + j];
    }
    __syncthreads();
    float a[LRANK];
#pragma unroll
    for (int r = 0; r < LRANK; r += 4) {
        float4 v = *reinterpret_cast<const float4*>(lA + (size_t)k * LRANK + r);
        a[r] = v.x; a[r + 1] = v.y; a[r + 2] = v.z; a[r + 3] = v.w;
    }
    const float sc = scale[0];
#pragma unroll 4
    for (int j = 0; j < 32; ++j) {
        const int nn = n0 + j;
        float s = (float)q[(size_t)nn * K_TOTAL + k] * sc;
#pragma unroll
        for (int r = 0; r < LRANK; ++r) s = fmaf(a[r], bs[r][j], s);
        g_weff[(size_t)nn * K_TOTAL + k] = __float2half_rn(s);
    }
}

// ---------------------------------------------------------------------------
// Stage loader: A [128 x 64h] + B [128 x 64h], SW128 swizzled, 16B cp.async,
// 128 threads -> 16 chunks/thread.
// ---------------------------------------------------------------------------
__device__ __forceinline__ void load_stage(uint32_t sb, const __half* gA,
                                           const __half* gB, int ks, int buf,
                                           int tid) {
    const __half* a = gA + (size_t)ks * BLOCK_K;
    const __half* b = gB + (size_t)ks * BLOCK_K;
    const uint32_t baseA = sb + buf * STAGE_BYTES;
    const uint32_t baseB = baseA + A_BYTES;
#pragma unroll
    for (int i = 0; i < 8; ++i) {                 // 1024 A chunks
        int c = tid + i * 128;
        int r = c >> 3, cc = c & 7;
        cp16(baseA + swz((uint32_t)(r * 128 + cc * 16)),
             a + (size_t)r * K_TOTAL + cc * 8);
    }
#pragma unroll
    for (int i = 0; i < 8; ++i) {                 // 1024 B chunks
        int c = tid + i * 128;
        int r = c >> 3, cc = c & 7;
        cp16(baseB + swz((uint32_t)(r * 128 + cc * 16)),
             b + (size_t)r * K_TOTAL + cc * 8);
    }
}

// ---------------------------------------------------------------------------
// Main GEMM: 128x128 CTA tile, 128 threads, 2 CTAs/SM, 3-deep cp.async
// pipeline, ONE __syncthreads per stage, loads issued BEFORE compute,
// double-buffered ldmatrix fragments across k16 steps.
// WAR safety: top-of-iter barrier of iter ks proves all warps finished
// compute of stage ks-1; the load in iter ks targets buffer (ks+2)%3 =
// (ks-1)%3, whose last reader was stage ks-1. Safe.
// ---------------------------------------------------------------------------
__global__ void __launch_bounds__(128, 2)
qlora_gemm_kernel(const float* __restrict__ bias, float* __restrict__ out) {
    extern __shared__ __align__(1024) char smem[];
    const uint32_t sb = (smem_to_u32(smem) + 1023u) & ~1023u;
    const int tid  = threadIdx.x;
    const int wid  = tid >> 5;
    const int lane = tid & 31;
    const int wm = (wid & 1) * 64;                // warp M offset in tile
    const int wn = (wid >> 1) * 64;               // warp N offset in tile
    const int n0 = blockIdx.x * BLOCK_N;
    const int m0 = blockIdx.y * BLOCK_M;
    const __half* gA = g_xh   + (size_t)m0 * K_TOTAL;
    const __half* gB = g_weff + (size_t)n0 * K_TOTAL;

    float acc[4][8][4];
#pragma unroll
    for (int mt = 0; mt < 4; ++mt)
#pragma unroll
        for (int nt = 0; nt < 8; ++nt)
#pragma unroll
            for (int r = 0; r < 4; ++r) acc[mt][nt][r] = 0.f;

    // ldmatrix lane geometry (fixed per thread)
    const int a_row = wm + (lane & 15);           // + mt*16
    const int a_kof = (lane >> 4) * 8;            // + j*16
    const int g     = lane >> 3;
    const int b_row = wn + ((g >> 1) & 1) * 8 + (lane & 7);  // + bt*16
    const int b_kof = (g & 1) * 8;                // + j*16

    // Prologue: stages 0..DEPTH-2
#pragma unroll
    for (int s = 0; s < DEPTH - 1; ++s) {
        load_stage(sb, gA, gB, s, s, tid);
        asm volatile("cp.async.commit_group;" ::: "memory");
    }

    uint32_t afr[2][4][4], bfr[2][4][4];

    for (int ks = 0; ks < NSTAGES; ++ks) {
        asm volatile("cp.async.wait_group %0;" :: "n"(DEPTH - 2) : "memory");
        __syncthreads();

        // Issue next stage's loads FIRST so the fetch overlaps this compute.
        const int nxt = ks + DEPTH - 1;
        if (nxt < NSTAGES)
            load_stage(sb, gA, gB, nxt, nxt % DEPTH, tid);
        asm volatile("cp.async.commit_group;" ::: "memory");  // may be empty

        const uint32_t bA = sb + (ks % DEPTH) * STAGE_BYTES;
        const uint32_t bB = bA + A_BYTES;

        // Preload fragments for j=0
#pragma unroll
        for (int mt = 0; mt < 4; ++mt)
            ldsm_x4(afr[0][mt], tile_addr(bA, a_row + mt * 16, a_kof));
#pragma unroll
        for (int bt = 0; bt < 4; ++bt)
            ldsm_x4(bfr[0][bt], tile_addr(bB, b_row + bt * 16, b_kof));

#pragma unroll
        for (int j = 0; j < 4; ++j) {             // k16 steps within stage
            const int cur = j & 1, nb = cur ^ 1;
            if (j < 3) {                          // prefetch j+1 fragments
#pragma unroll
                for (int mt = 0; mt < 4; ++mt)
                    ldsm_x4(afr[nb][mt],
                            tile_addr(bA, a_row + mt * 16, (j + 1) * 16 + a_kof));
#pragma unroll
                for (int bt = 0; bt < 4; ++bt)
                    ldsm_x4(bfr[nb][bt],
                            tile_addr(bB, b_row + bt * 16, (j + 1) * 16 + b_kof));
            }
#pragma unroll
            for (int mt = 0; mt < 4; ++mt)
#pragma unroll
                for (int bt = 0; bt < 4; ++bt) {
                    mma16816(acc[mt][2 * bt],     afr[cur][mt], &bfr[cur][bt][0]);
                    mma16816(acc[mt][2 * bt + 1], afr[cur][mt], &bfr[cur][bt][2]);
                }
        }
    }

    // Epilogue: bias + fp32 stores (mma d layout: rows t/4, t/4+8; cols
    // 2*(t%4), 2*(t%4)+1 within each 16x8 tile)
    const int er = lane >> 2;
    const int ec = (lane & 3) * 2;
#pragma unroll
    for (int mt = 0; mt < 4; ++mt) {
        const int r0 = m0 + wm + mt * 16 + er;
        float* o0 = out + (size_t)r0 * N_TOTAL;
        float* o1 = o0 + 8 * N_TOTAL;
#pragma unroll
        for (int nt = 0; nt < 8; ++nt) {
            const int n = n0 + wn + nt * 8 + ec;
            const float2 bv = *reinterpret_cast<const float2*>(bias + n);
            float2 v0, v1;
            v0.x = acc[mt][nt][0] + bv.x;
            v0.y = acc[mt][nt][1] + bv.y;
            v1.x = acc[mt][nt][2] + bv.x;
            v1.y = acc[mt][nt][3] + bv.y;
            *reinterpret_cast<float2*>(o0 + n) = v0;
            *reinterpret_cast<float2*>(o1 + n) = v1;
        }
    }
}

// ---------------------------------------------------------------------------
// kernel_launch
// Inputs: 0=x f32 [4,2048,4096], 1=qweight i32 [4096,4096], 2=scales f32 [1],
//         3=bias f32 [4096], 4=lora_A f32 [4096,16], 5=lora_B f32 [16,4096]
// Output: f32 [4,2048,4096]
// ---------------------------------------------------------------------------
extern "C" void kernel_launch(void* const* d_in, const int* in_sizes, int n_in,
                              void* d_out, int out_size) {
    const float* x    = (const float*)d_in[0];
    const int*   q    = (const int*)d_in[1];
    const float* sc   = (const float*)d_in[2];
    const float* bias = (const float*)d_in[3];
    const float* lA   = (const float*)d_in[4];
    const float* lB   = (const float*)d_in[5];
    float* out = (float*)d_out;
    (void)in_sizes; (void)n_in; (void)out_size;

    cudaFuncSetAttribute(qlora_gemm_kernel,
                         cudaFuncAttributeMaxDynamicSharedMemorySize, SMEM_DYN);

    // 1) fused prep: x->fp16 AND W_eff = scale*q + A@B (concurrent)
    prep_kernel<<<CVT_BLOCKS + WEFF_BLOCKS, 256>>>(
        (const float4*)x, q, sc, lA, lB);
    // 2) GEMM + bias
    qlora_gemm_kernel<<<dim3(N_TOTAL / BLOCK_N, M_TOTAL / BLOCK_M), 128,
                        SMEM_DYN>>>(bias, out);
}

// round 14
// speedup vs baseline: 1.0324x; 1.0324x over previous
#include <cuda_runtime.h>
#include <cuda_fp16.h>
#include <cuda_bf16.h>
#include <cstdint>
#include <cstddef>

// ---------------------------------------------------------------------------
// out[8192,4096] = x[8192,4096] @ W_eff[4096,4096]^T + bias
//   W_eff = scale*qweight + lora_A @ lora_B   (LoRA folded into the weight)
// Base-ISA path (harness compiles compute_103, no 'a' features):
//   cp.async + ldmatrix + mma.sync.m16n8k16 f16->f32.
// R14 vs R13: prep kernel schedules the latency-bound W_eff blocks FIRST so
// they overlap the DRAM-bound x-conversion stream (they trailed it before);
// streaming loads for single-use x. GEMM mainloop unchanged (575us, 78.7%
// tensor — measured best).
// ---------------------------------------------------------------------------
#define M_TOTAL 8192
#define K_TOTAL 4096
#define N_TOTAL 4096
#define LRANK   16

#define BLOCK_M 128
#define BLOCK_N 128
#define BLOCK_K 64                       // halves per stage
#define NSTAGES (K_TOTAL / BLOCK_K)      // 64
#define DEPTH   3

#define A_BYTES (BLOCK_M * BLOCK_K * 2)  // 16384
#define B_BYTES (BLOCK_N * BLOCK_K * 2)  // 16384
#define STAGE_BYTES (A_BYTES + B_BYTES)  // 32768
#define SMEM_DYN (DEPTH * STAGE_BYTES + 1024)   // 99328

// 4 warps = 2 (M) x 2 (N); warp tile 64 x 64 (4 m16 x 8 n8 mma tiles).

// Fused prep grid split: W_eff blocks FIRST (latency-bound, overlap cvt)
#define WEFF_BX     (K_TOTAL / 256)      // 16
#define WEFF_BY     (N_TOTAL / 32)       // 128
#define WEFF_BLOCKS (WEFF_BX * WEFF_BY)  // 2048
#define CVT_BLOCKS  16384                // (M*K/8)/256

// ---------------------------------------------------------------------------
// Scratch (static device globals: allocation-free rule)
// ---------------------------------------------------------------------------
__device__ __align__(1024) __half g_xh[(size_t)M_TOTAL * K_TOTAL];    // 64 MB
__device__ __align__(1024) __half g_weff[(size_t)N_TOTAL * K_TOTAL];  // 32 MB

// ---------------------------------------------------------------------------
// Helpers
// ---------------------------------------------------------------------------
__device__ __forceinline__ uint32_t smem_to_u32(const void* p) {
    uint32_t a;
    asm("{ .reg .u64 t; cvta.to.shared.u64 t, %1; cvt.u32.u64 %0, t; }"
        : "=r"(a) : "l"(p));
    return a;
}

__device__ __forceinline__ void cp16(uint32_t dst, const void* src) {
    asm volatile("cp.async.cg.shared.global [%0], [%1], 16;"
                 :: "r"(dst), "l"(src) : "memory");
}

// SW128 swizzle for 128-byte rows: XOR bits[6:4] with bits[9:7]
__device__ __forceinline__ uint32_t swz(uint32_t byte) {
    return byte ^ ((byte >> 3) & 0x70);
}

__device__ __forceinline__ uint32_t tile_addr(uint32_t base, int row, int kcol) {
    return base + swz((uint32_t)(row * 128 + kcol * 2));
}

__device__ __forceinline__ void ldsm_x4(uint32_t* r, uint32_t addr) {
    asm volatile("ldmatrix.sync.aligned.m8n8.x4.shared.b16 {%0,%1,%2,%3}, [%4];"
                 : "=r"(r[0]), "=r"(r[1]), "=r"(r[2]), "=r"(r[3]) : "r"(addr));
}

__device__ __forceinline__ void mma16816(float* c, const uint32_t* a,
                                         const uint32_t* b) {
    asm volatile(
        "mma.sync.aligned.m16n8k16.row.col.f32.f16.f16.f32 "
        "{%0,%1,%2,%3}, {%4,%5,%6,%7}, {%8,%9}, {%0,%1,%2,%3};"
        : "+f"(c[0]), "+f"(c[1]), "+f"(c[2]), "+f"(c[3])
        : "r"(a[0]), "r"(a[1]), "r"(a[2]), "r"(a[3]), "r"(b[0]), "r"(b[1]));
}

// Streaming fp32x4 load (single-use data, evict-first)
__device__ __forceinline__ float4 ldg_cs4(const float4* p) {
    float4 v;
    asm volatile("ld.global.cs.v4.f32 {%0,%1,%2,%3}, [%4];"
                 : "=f"(v.x), "=f"(v.y), "=f"(v.z), "=f"(v.w) : "l"(p));
    return v;
}

// ---------------------------------------------------------------------------
// Fused prep: blocks [0, WEFF_BLOCKS) build W_eff (latency-bound, start
// first); blocks [WEFF_BLOCKS, +CVT_BLOCKS) convert x fp32->fp16 (DRAM-bound,
// fills the machine while weff chains retire).
// ---------------------------------------------------------------------------
__global__ void __launch_bounds__(256) prep_kernel(
        const float4* __restrict__ x,
        const int* __restrict__ q, const float* __restrict__ scale,
        const float* __restrict__ lA, const float* __restrict__ lB) {
    if (blockIdx.x >= WEFF_BLOCKS) {
        size_t i = (size_t)(blockIdx.x - WEFF_BLOCKS) * 256 + threadIdx.x;
        float4 a = ldg_cs4(x + 2 * i);
        float4 b = ldg_cs4(x + 2 * i + 1);
        __half2 h0 = __floats2half2_rn(a.x, a.y);
        __half2 h1 = __floats2half2_rn(a.z, a.w);
        __half2 h2 = __floats2half2_rn(b.x, b.y);
        __half2 h3 = __floats2half2_rn(b.z, b.w);
        uint4 o;
        o.x = *reinterpret_cast<uint32_t*>(&h0);
        o.y = *reinterpret_cast<uint32_t*>(&h1);
        o.z = *reinterpret_cast<uint32_t*>(&h2);
        o.w = *reinterpret_cast<uint32_t*>(&h3);
        reinterpret_cast<uint4*>(g_xh)[i] = o;
        return;
    }
    // W_eff part
    __shared__ float bs[LRANK][33];
    const int b  = blockIdx.x;
    const int k  = (b % WEFF_BX) * 256 + threadIdx.x;
    const int n0 = (b / WEFF_BX) * 32;
    for (int idx = threadIdx.x; idx < LRANK * 32; idx += 256) {
        int r = idx >> 5, j = idx & 31;
        bs[r][j] = lB[r * N_TOTAL + n0 + j];
    }
    __syncthreads();
    float a[LRANK];
#pragma unroll
    for (int r = 0; r < LRANK; r += 4) {
        float4 v = *reinterpret_cast<const float4*>(lA + (size_t)k * LRANK + r);
        a[r] = v.x; a[r + 1] = v.y; a[r + 2] = v.z; a[r + 3] = v.w;
    }
    const float sc = scale[0];
#pragma unroll 4
    for (int j = 0; j < 32; ++j) {
        const int nn = n0 + j;
        float s = (float)q[(size_t)nn * K_TOTAL + k] * sc;
#pragma unroll
        for (int r = 0; r < LRANK; ++r) s = fmaf(a[r], bs[r][j], s);
        g_weff[(size_t)nn * K_TOTAL + k] = __float2half_rn(s);
    }
}

// ---------------------------------------------------------------------------
// Stage loader: A [128 x 64h] + B [128 x 64h], SW128 swizzled, 16B cp.async,
// 128 threads -> 16 chunks/thread.
// ---------------------------------------------------------------------------
__device__ __forceinline__ void load_stage(uint32_t sb, const __half* gA,
                                           const __half* gB, int ks, int buf,
                                           int tid) {
    const __half* a = gA + (size_t)ks * BLOCK_K;
    const __half* b = gB + (size_t)ks * BLOCK_K;
    const uint32_t baseA = sb + buf * STAGE_BYTES;
    const uint32_t baseB = baseA + A_BYTES;
#pragma unroll
    for (int i = 0; i < 8; ++i) {                 // 1024 A chunks
        int c = tid + i * 128;
        int r = c >> 3, cc = c & 7;
        cp16(baseA + swz((uint32_t)(r * 128 + cc * 16)),
             a + (size_t)r * K_TOTAL + cc * 8);
    }
#pragma unroll
    for (int i = 0; i < 8; ++i) {                 // 1024 B chunks
        int c = tid + i * 128;
        int r = c >> 3, cc = c & 7;
        cp16(baseB + swz((uint32_t)(r * 128 + cc * 16)),
             b + (size_t)r * K_TOTAL + cc * 8);
    }
}

// ---------------------------------------------------------------------------
// Main GEMM: 128x128 CTA tile, 128 threads, 2 CTAs/SM, 3-deep cp.async
// pipeline, ONE __syncthreads per stage, loads issued BEFORE compute,
// double-buffered ldmatrix fragments across k16 steps.  (Measured: 575us,
// tensor 78.7% -- unchanged this round.)
// WAR safety: top-of-iter barrier of iter ks proves all warps finished
// compute of stage ks-1; the load in iter ks targets buffer (ks+2)%3 =
// (ks-1)%3, whose last reader was stage ks-1. Safe.
// ---------------------------------------------------------------------------
__global__ void __launch_bounds__(128, 2)
qlora_gemm_kernel(const float* __restrict__ bias, float* __restrict__ out) {
    extern __shared__ __align__(1024) char smem[];
    const uint32_t sb = (smem_to_u32(smem) + 1023u) & ~1023u;
    const int tid  = threadIdx.x;
    const int wid  = tid >> 5;
    const int lane = tid & 31;
    const int wm = (wid & 1) * 64;                // warp M offset in tile
    const int wn = (wid >> 1) * 64;               // warp N offset in tile
    const int n0 = blockIdx.x * BLOCK_N;
    const int m0 = blockIdx.y * BLOCK_M;
    const __half* gA = g_xh   + (size_t)m0 * K_TOTAL;
    const __half* gB = g_weff + (size_t)n0 * K_TOTAL;

    float acc[4][8][4];
#pragma unroll
    for (int mt = 0; mt < 4; ++mt)
#pragma unroll
        for (int nt = 0; nt < 8; ++nt)
#pragma unroll
            for (int r = 0; r < 4; ++r) acc[mt][nt][r] = 0.f;

    // ldmatrix lane geometry (fixed per thread)
    const int a_row = wm + (lane & 15);           // + mt*16
    const int a_kof = (lane >> 4) * 8;            // + j*16
    const int g     = lane >> 3;
    const int b_row = wn + ((g >> 1) & 1) * 8 + (lane & 7);  // + bt*16
    const int b_kof = (g & 1) * 8;                // + j*16

    // Prologue: stages 0..DEPTH-2
#pragma unroll
    for (int s = 0; s < DEPTH - 1; ++s) {
        load_stage(sb, gA, gB, s, s, tid);
        asm volatile("cp.async.commit_group;" ::: "memory");
    }

    uint32_t afr[2][4][4], bfr[2][4][4];

    for (int ks = 0; ks < NSTAGES; ++ks) {
        asm volatile("cp.async.wait_group %0;" :: "n"(DEPTH - 2) : "memory");
        __syncthreads();

        // Issue next stage's loads FIRST so the fetch overlaps this compute.
        const int nxt = ks + DEPTH - 1;
        if (nxt < NSTAGES)
            load_stage(sb, gA, gB, nxt, nxt % DEPTH, tid);
        asm volatile("cp.async.commit_group;" ::: "memory");  // may be empty

        const uint32_t bA = sb + (ks % DEPTH) * STAGE_BYTES;
        const uint32_t bB = bA + A_BYTES;

        // Preload fragments for j=0
#pragma unroll
        for (int mt = 0; mt < 4; ++mt)
            ldsm_x4(afr[0][mt], tile_addr(bA, a_row + mt * 16, a_kof));
#pragma unroll
        for (int bt = 0; bt < 4; ++bt)
            ldsm_x4(bfr[0][bt], tile_addr(bB, b_row + bt * 16, b_kof));

#pragma unroll
        for (int j = 0; j < 4; ++j) {             // k16 steps within stage
            const int cur = j & 1, nb = cur ^ 1;
            if (j < 3) {                          // prefetch j+1 fragments
#pragma unroll
                for (int mt = 0; mt < 4; ++mt)
                    ldsm_x4(afr[nb][mt],
                            tile_addr(bA, a_row + mt * 16, (j + 1) * 16 + a_kof));
#pragma unroll
                for (int bt = 0; bt < 4; ++bt)
                    ldsm_x4(bfr[nb][bt],
                            tile_addr(bB, b_row + bt * 16, (j + 1) * 16 + b_kof));
            }
#pragma unroll
            for (int mt = 0; mt < 4; ++mt)
#pragma unroll
                for (int bt = 0; bt < 4; ++bt) {
                    mma16816(acc[mt][2 * bt],     afr[cur][mt], &bfr[cur][bt][0]);
                    mma16816(acc[mt][2 * bt + 1], afr[cur][mt], &bfr[cur][bt][2]);
                }
        }
    }

    // Epilogue: bias + fp32 stores (mma d layout: rows t/4, t/4+8; cols
    // 2*(t%4), 2*(t%4)+1 within each 16x8 tile)
    const int er = lane >> 2;
    const int ec = (lane & 3) * 2;
#pragma unroll
    for (int mt = 0; mt < 4; ++mt) {
        const int r0 = m0 + wm + mt * 16 + er;
        float* o0 = out + (size_t)r0 * N_TOTAL;
        float* o1 = o0 + 8 * N_TOTAL;
#pragma unroll
        for (int nt = 0; nt < 8; ++nt) {
            const int n = n0 + wn + nt * 8 + ec;
            const float2 bv = *reinterpret_cast<const float2*>(bias + n);
            float2 v0, v1;
            v0.x = acc[mt][nt][0] + bv.x;
            v0.y = acc[mt][nt][1] + bv.y;
            v1.x = acc[mt][nt][2] + bv.x;
            v1.y = acc[mt][nt][3] + bv.y;
            *reinterpret_cast<float2*>(o0 + n) = v0;
            *reinterpret_cast<float2*>(o1 + n) = v1;
        }
    }
}

// ---------------------------------------------------------------------------
// kernel_launch
// Inputs: 0=x f32 [4,2048,4096], 1=qweight i32 [4096,4096], 2=scales f32 [1],
//         3=bias f32 [4096], 4=lora_A f32 [4096,16], 5=lora_B f32 [16,4096]
// Output: f32 [4,2048,4096]
// ---------------------------------------------------------------------------
extern "C" void kernel_launch(void* const* d_in, const int* in_sizes, int n_in,
                              void* d_out, int out_size) {
    const float* x    = (const float*)d_in[0];
    const int*   q    = (const int*)d_in[1];
    const float* sc   = (const float*)d_in[2];
    const float* bias = (const float*)d_in[3];
    const float* lA   = (const float*)d_in[4];
    const float* lB   = (const float*)d_in[5];
    float* out = (float*)d_out;
    (void)in_sizes; (void)n_in; (void)out_size;

    cudaFuncSetAttribute(qlora_gemm_kernel,
                         cudaFuncAttributeMaxDynamicSharedMemorySize, SMEM_DYN);

    // 1) fused prep: W_eff blocks first (latency-bound), then x->fp16
    prep_kernel<<<WEFF_BLOCKS + CVT_BLOCKS, 256>>>(
        (const float4*)x, q, sc, lA, lB);
    // 2) GEMM + bias
    qlora_gemm_kernel<<<dim3(N_TOTAL / BLOCK_N, M_TOTAL / BLOCK_M), 128,
                        SMEM_DYN>>>(bias, out);
}